// round 1
// baseline (speedup 1.0000x reference)
#include <cuda_runtime.h>
#include <math.h>

// Problem constants
#define BB  2
#define SS  2048
#define DD  512
#define HH  8
#define HIDV 512
#define DHV 64

// Scratch (static device arrays: allocation-free rule)
__device__ float g_qp[BB * SS * HIDV];
__device__ float g_kp[BB * SS * HIDV];
__device__ float g_vp[BB * SS * HIDV];
__device__ float g_ctx[BB * SS * HIDV];

// ---------------------------------------------------------------------------
// SGEMM: C[M,N] = A[M,K] @ W[K,N] + bias[N]
// BM=128, BN=128, BK=8, 256 threads, 8x8 register tile per thread
// ---------------------------------------------------------------------------
#define BM 128
#define BN 128
#define BKK 8
#define TM 8
#define TN 8

__device__ __forceinline__ void sgemm_body(const float* __restrict__ A,
                                           const float* __restrict__ W,
                                           const float* __restrict__ bias,
                                           float* __restrict__ C,
                                           int M, int N, int K) {
    __shared__ float As[BKK][BM];
    __shared__ float Ws[BKK][BN];

    const int tid = threadIdx.x;
    const int block_row = blockIdx.x * BM;
    const int block_col = blockIdx.y * BN;

    const int tx = tid & 15;        // 0..15
    const int ty = tid >> 4;        // 0..15

    float acc[TM][TN];
#pragma unroll
    for (int i = 0; i < TM; i++)
#pragma unroll
        for (int j = 0; j < TN; j++) acc[i][j] = 0.f;

    // A-tile load map: 128x8 floats, 256 threads x float4
    const int a_row = tid >> 1;            // 0..127
    const int a_col = (tid & 1) * 4;       // 0 or 4
    // W-tile load map: 8x128 floats
    const int w_row = tid >> 5;            // 0..7
    const int w_col = (tid & 31) * 4;      // 0..124

    for (int k0 = 0; k0 < K; k0 += BKK) {
        float4 a4 = *(const float4*)&A[(size_t)(block_row + a_row) * K + k0 + a_col];
        As[a_col + 0][a_row] = a4.x;
        As[a_col + 1][a_row] = a4.y;
        As[a_col + 2][a_row] = a4.z;
        As[a_col + 3][a_row] = a4.w;
        *(float4*)&Ws[w_row][w_col] =
            *(const float4*)&W[(size_t)(k0 + w_row) * N + block_col + w_col];
        __syncthreads();

#pragma unroll
        for (int kk = 0; kk < BKK; kk++) {
            float ra[TM], rb[TN];
#pragma unroll
            for (int i = 0; i < TM; i++) ra[i] = As[kk][ty * TM + i];
#pragma unroll
            for (int j = 0; j < TN; j++) rb[j] = Ws[kk][tx * TN + j];
#pragma unroll
            for (int i = 0; i < TM; i++)
#pragma unroll
                for (int j = 0; j < TN; j++) acc[i][j] += ra[i] * rb[j];
        }
        __syncthreads();
    }

#pragma unroll
    for (int i = 0; i < TM; i++) {
        const int r = block_row + ty * TM + i;
#pragma unroll
        for (int j = 0; j < TN; j += 4) {
            const int c = block_col + tx * TN + j;
            float4 o;
            o.x = acc[i][j + 0] + bias[c + 0];
            o.y = acc[i][j + 1] + bias[c + 1];
            o.z = acc[i][j + 2] + bias[c + 2];
            o.w = acc[i][j + 3] + bias[c + 3];
            *(float4*)&C[(size_t)r * N + c] = o;
        }
    }
}

__global__ __launch_bounds__(256) void proj_kernel(
    const float* __restrict__ q, const float* __restrict__ k, const float* __restrict__ v,
    const float* __restrict__ Wq, const float* __restrict__ bq,
    const float* __restrict__ Wk, const float* __restrict__ bk,
    const float* __restrict__ Wv, const float* __restrict__ bv) {
    const float* A;
    const float* W;
    const float* bias;
    float* C;
    if (blockIdx.z == 0) { A = q; W = Wq; bias = bq; C = g_qp; }
    else if (blockIdx.z == 1) { A = k; W = Wk; bias = bk; C = g_kp; }
    else { A = v; W = Wv; bias = bv; C = g_vp; }
    sgemm_body(A, W, bias, C, BB * SS, HIDV, DD);
}

__global__ __launch_bounds__(256) void out_gemm_kernel(
    const float* __restrict__ Wo, const float* __restrict__ bo, float* __restrict__ out) {
    sgemm_body(g_ctx, Wo, bo, out, BB * SS, DD, HIDV);
}

// ---------------------------------------------------------------------------
// Flash attention, 64x64 tiles, online softmax, fp32.
// Head h of batch b is the contiguous slab g_qp + (b*H + h)*S*DH (raw reshape).
// Reference applies 1/sqrt(DH) AFTER softmax -> fold into final normalization.
// ---------------------------------------------------------------------------
#define AQ 64
#define AK 64
#define SPAD 68   // row stride in floats (padding vs 64 to dodge bank conflicts)

__global__ __launch_bounds__(256) void attn_kernel() {
    extern __shared__ float sm[];
    float* sQ = sm;                 // AQ x SPAD
    float* sK = sQ + AQ * SPAD;     // AK x SPAD
    float* sV = sK + AK * SPAD;     // AK x SPAD
    float* sP = sV + AK * SPAD;     // AQ x SPAD

    const int b = blockIdx.z;
    const int h = blockIdx.y;
    const int q0 = blockIdx.x * AQ;

    const float* Qh = g_qp + ((size_t)b * HH + h) * SS * DHV;
    const float* Kh = g_kp + ((size_t)b * HH + h) * SS * DHV;
    const float* Vh = g_vp + ((size_t)b * HH + h) * SS * DHV;

    const int tid = threadIdx.x;
    const int tx = tid & 15;   // score col group
    const int ty = tid >> 4;   // score row group

    // Load Q tile (64 rows x 64 floats)
    for (int i = tid; i < AQ * (DHV / 4); i += 256) {
        const int r = i >> 4;
        const int c4 = (i & 15) * 4;
        *(float4*)&sQ[r * SPAD + c4] = *(const float4*)&Qh[(size_t)(q0 + r) * DHV + c4];
    }

    float m[4], l[4], o[4][4];
#pragma unroll
    for (int i = 0; i < 4; i++) {
        m[i] = -1e30f;
        l[i] = 0.f;
#pragma unroll
        for (int j = 0; j < 4; j++) o[i][j] = 0.f;
    }

    for (int t = 0; t < SS; t += AK) {
        __syncthreads();  // protect sK/sV/sP reuse from previous iteration
        for (int i = tid; i < AK * (DHV / 4); i += 256) {
            const int r = i >> 4;
            const int c4 = (i & 15) * 4;
            *(float4*)&sK[r * SPAD + c4] = *(const float4*)&Kh[(size_t)(t + r) * DHV + c4];
            *(float4*)&sV[r * SPAD + c4] = *(const float4*)&Vh[(size_t)(t + r) * DHV + c4];
        }
        __syncthreads();

        // scores: S = Q @ K^T (4x4 per thread)
        float s[4][4];
#pragma unroll
        for (int i = 0; i < 4; i++)
#pragma unroll
            for (int j = 0; j < 4; j++) s[i][j] = 0.f;

#pragma unroll 4
        for (int d = 0; d < DHV; d++) {
            float ra[4], rb[4];
#pragma unroll
            for (int i = 0; i < 4; i++) ra[i] = sQ[(ty * 4 + i) * SPAD + d];
#pragma unroll
            for (int j = 0; j < 4; j++) rb[j] = sK[(tx * 4 + j) * SPAD + d];
#pragma unroll
            for (int i = 0; i < 4; i++)
#pragma unroll
                for (int j = 0; j < 4; j++) s[i][j] += ra[i] * rb[j];
        }

        // Online softmax per row; row is split across the 16 tx lanes of a half-warp.
#pragma unroll
        for (int i = 0; i < 4; i++) {
            float mx = fmaxf(fmaxf(s[i][0], s[i][1]), fmaxf(s[i][2], s[i][3]));
#pragma unroll
            for (int w = 8; w >= 1; w >>= 1)
                mx = fmaxf(mx, __shfl_xor_sync(0xffffffffu, mx, w));
            const float mn = fmaxf(m[i], mx);
            const float alpha = __expf(m[i] - mn);
            float sum = 0.f;
#pragma unroll
            for (int j = 0; j < 4; j++) {
                s[i][j] = __expf(s[i][j] - mn);
                sum += s[i][j];
            }
#pragma unroll
            for (int w = 8; w >= 1; w >>= 1)
                sum += __shfl_xor_sync(0xffffffffu, sum, w);
            l[i] = l[i] * alpha + sum;
            m[i] = mn;
#pragma unroll
            for (int j = 0; j < 4; j++) o[i][j] *= alpha;
#pragma unroll
            for (int j = 0; j < 4; j++) sP[(ty * 4 + i) * SPAD + tx * 4 + j] = s[i][j];
        }
        __syncthreads();

        // O += P @ V
#pragma unroll 4
        for (int c = 0; c < AK; c++) {
            float rp[4], rv[4];
#pragma unroll
            for (int i = 0; i < 4; i++) rp[i] = sP[(ty * 4 + i) * SPAD + c];
#pragma unroll
            for (int j = 0; j < 4; j++) rv[j] = sV[c * SPAD + tx * 4 + j];
#pragma unroll
            for (int i = 0; i < 4; i++)
#pragma unroll
                for (int j = 0; j < 4; j++) o[i][j] += rp[i] * rv[j];
        }
    }

    // Epilogue: ctx[b][s][h*DH + d] = O / (l * sqrt(DH)); sqrt(64)=8 applied
    // post-softmax per the reference. The head-concat transpose is folded into
    // the store address so the output GEMM reads a contiguous [B*S, HID] matrix.
#pragma unroll
    for (int i = 0; i < 4; i++) {
        const int srow = q0 + ty * 4 + i;
        const float inv = 1.0f / (l[i] * 8.0f);
        float* dst = g_ctx + ((size_t)b * SS + srow) * HIDV + h * DHV + tx * 4;
#pragma unroll
        for (int j = 0; j < 4; j++) dst[j] = o[i][j] * inv;
    }
}

// ---------------------------------------------------------------------------
extern "C" void kernel_launch(void* const* d_in, const int* in_sizes, int n_in,
                              void* d_out, int out_size) {
    (void)in_sizes; (void)n_in; (void)out_size;
    const float* q  = (const float*)d_in[0];
    const float* k  = (const float*)d_in[1];
    const float* v  = (const float*)d_in[2];
    const float* Wq = (const float*)d_in[3];
    const float* bq = (const float*)d_in[4];
    const float* Wk = (const float*)d_in[5];
    const float* bk = (const float*)d_in[6];
    const float* Wv = (const float*)d_in[7];
    const float* bv = (const float*)d_in[8];
    const float* Wo = (const float*)d_in[9];
    const float* bo = (const float*)d_in[10];
    float* out = (float*)d_out;

    // 1) fused QKV projections: [4096,512] @ [512,512] x3
    dim3 pg(BB * SS / BM, HIDV / BN, 3);
    proj_kernel<<<pg, 256>>>(q, k, v, Wq, bq, Wk, bk, Wv, bv);

    // 2) flash attention per (qtile, head, batch)
    const size_t smem = (size_t)(AQ + AK + AK + AQ) * SPAD * sizeof(float);
    cudaFuncSetAttribute(attn_kernel, cudaFuncAttributeMaxDynamicSharedMemorySize,
                         (int)smem);
    attn_kernel<<<dim3(SS / AQ, HH, BB), 256, smem>>>();

    // 3) output projection: [4096,512] @ [512,512]
    dim3 og(BB * SS / BM, DD / BN, 1);
    out_gemm_kernel<<<og, 256>>>(Wo, bo, out);
}

// round 2
// speedup vs baseline: 4.8861x; 4.8861x over previous
#include <cuda_runtime.h>
#include <math.h>
#include <stdint.h>

// Problem constants
#define BB  2
#define SS  2048
#define DD  512
#define HH  8
#define HIDV 512
#define DHV 64

// Scratch
__device__ float g_qp[BB * SS * HIDV];
__device__ float g_kp[BB * SS * HIDV];
__device__ float g_vp[BB * SS * HIDV];
__device__ float g_ctx[BB * SS * HIDV];

// ---------------------------------------------------------------------------
// tf32 helpers
// ---------------------------------------------------------------------------
__device__ __forceinline__ uint32_t f2tf32(float x) {
    uint32_t u;
    asm("cvt.rna.tf32.f32 %0, %1;" : "=r"(u) : "f"(x));
    return u;
}

__device__ __forceinline__ void mma_tf32(float c[4], const uint32_t a[4],
                                         const uint32_t b[2]) {
    asm volatile(
        "mma.sync.aligned.m16n8k8.row.col.f32.tf32.tf32.f32 "
        "{%0,%1,%2,%3}, {%4,%5,%6,%7}, {%8,%9}, {%0,%1,%2,%3};"
        : "+f"(c[0]), "+f"(c[1]), "+f"(c[2]), "+f"(c[3])
        : "r"(a[0]), "r"(a[1]), "r"(a[2]), "r"(a[3]), "r"(b[0]), "r"(b[1]));
}

// ---------------------------------------------------------------------------
// tf32 GEMM: C[M,N] = A[M,K] @ W[K,N] + bias
// 128x128x32 block tile, 8 warps (2x4), warp tile 64x32 (4 m-tiles x 4 n-tiles)
// ---------------------------------------------------------------------------
#define GSA 36    // sA row stride (bank-conflict-free frag loads: (4g+tig)%32)
#define GSB 136   // sB row stride (bank-conflict-free: (8*tig+g)%32)

__device__ __forceinline__ void gemm_tf32_body(const float* __restrict__ A,
                                               const float* __restrict__ W,
                                               const float* __restrict__ bias,
                                               float* __restrict__ C,
                                               int M, int N, int K) {
    __shared__ float sA[128][GSA];
    __shared__ float sB[32][GSB];

    const int tid = threadIdx.x;
    const int lane = tid & 31;
    const int warp = tid >> 5;
    const int g = lane >> 2;       // groupID 0..7
    const int tg = lane & 3;       // threadID_in_group 0..3
    const int wr = warp >> 2;      // 0..1
    const int wc = warp & 3;       // 0..3

    const int brow = blockIdx.x * 128;
    const int bcol = blockIdx.y * 128;

    float acc[4][4][4];
#pragma unroll
    for (int mt = 0; mt < 4; mt++)
#pragma unroll
        for (int nt = 0; nt < 4; nt++)
#pragma unroll
            for (int e = 0; e < 4; e++) acc[mt][nt][e] = 0.f;

    for (int k0 = 0; k0 < K; k0 += 32) {
        // A tile: 128 rows x 32 cols
#pragma unroll
        for (int i = 0; i < 4; i++) {
            int linear = tid + i * 256;
            int row = linear >> 3;
            int c4 = (linear & 7) * 4;
            float4 a4 = *(const float4*)&A[(size_t)(brow + row) * K + k0 + c4];
            sA[row][c4 + 0] = __uint_as_float(f2tf32(a4.x));
            sA[row][c4 + 1] = __uint_as_float(f2tf32(a4.y));
            sA[row][c4 + 2] = __uint_as_float(f2tf32(a4.z));
            sA[row][c4 + 3] = __uint_as_float(f2tf32(a4.w));
        }
        // B tile: 32 rows x 128 cols
#pragma unroll
        for (int i = 0; i < 4; i++) {
            int linear = tid + i * 256;
            int row = linear >> 5;
            int c4 = (linear & 31) * 4;
            float4 b4 = *(const float4*)&W[(size_t)(k0 + row) * N + bcol + c4];
            sB[row][c4 + 0] = __uint_as_float(f2tf32(b4.x));
            sB[row][c4 + 1] = __uint_as_float(f2tf32(b4.y));
            sB[row][c4 + 2] = __uint_as_float(f2tf32(b4.z));
            sB[row][c4 + 3] = __uint_as_float(f2tf32(b4.w));
        }
        __syncthreads();

#pragma unroll
        for (int ks = 0; ks < 4; ks++) {
            const int kk = ks * 8;
            uint32_t af[4][4];
#pragma unroll
            for (int mt = 0; mt < 4; mt++) {
                const int r = wr * 64 + mt * 16;
                af[mt][0] = __float_as_uint(sA[r + g][kk + tg]);
                af[mt][1] = __float_as_uint(sA[r + g + 8][kk + tg]);
                af[mt][2] = __float_as_uint(sA[r + g][kk + tg + 4]);
                af[mt][3] = __float_as_uint(sA[r + g + 8][kk + tg + 4]);
            }
#pragma unroll
            for (int nt = 0; nt < 4; nt++) {
                const int c = wc * 32 + nt * 8;
                uint32_t bf[2];
                bf[0] = __float_as_uint(sB[kk + tg][c + g]);
                bf[1] = __float_as_uint(sB[kk + tg + 4][c + g]);
#pragma unroll
                for (int mt = 0; mt < 4; mt++) mma_tf32(acc[mt][nt], af[mt], bf);
            }
        }
        __syncthreads();
    }

    // epilogue + bias
#pragma unroll
    for (int mt = 0; mt < 4; mt++) {
        const int r0 = brow + wr * 64 + mt * 16 + g;
#pragma unroll
        for (int nt = 0; nt < 4; nt++) {
            const int c = bcol + wc * 32 + nt * 8 + 2 * tg;
            float2 b2 = *(const float2*)&bias[c];
            float2 o0, o1;
            o0.x = acc[mt][nt][0] + b2.x;
            o0.y = acc[mt][nt][1] + b2.y;
            o1.x = acc[mt][nt][2] + b2.x;
            o1.y = acc[mt][nt][3] + b2.y;
            *(float2*)&C[(size_t)r0 * N + c] = o0;
            *(float2*)&C[(size_t)(r0 + 8) * N + c] = o1;
        }
    }
}

__global__ __launch_bounds__(256) void proj_kernel(
    const float* __restrict__ q, const float* __restrict__ k, const float* __restrict__ v,
    const float* __restrict__ Wq, const float* __restrict__ bq,
    const float* __restrict__ Wk, const float* __restrict__ bk,
    const float* __restrict__ Wv, const float* __restrict__ bv) {
    const float* A; const float* W; const float* bias; float* C;
    if (blockIdx.z == 0)      { A = q; W = Wq; bias = bq; C = g_qp; }
    else if (blockIdx.z == 1) { A = k; W = Wk; bias = bk; C = g_kp; }
    else                      { A = v; W = Wv; bias = bv; C = g_vp; }
    gemm_tf32_body(A, W, bias, C, BB * SS, HIDV, DD);
}

__global__ __launch_bounds__(256) void out_gemm_kernel(
    const float* __restrict__ Wo, const float* __restrict__ bo, float* __restrict__ out) {
    gemm_tf32_body(g_ctx, Wo, bo, out, BB * SS, DD, HIDV);
}

// ---------------------------------------------------------------------------
// Flash attention with tf32 mma.
// Block: 128 q-rows, 4 warps (each 32 rows = 2 m-tiles), KV tiles of 64.
// Head h of batch b = contiguous slab (raw reshape). /sqrt(64) after softmax
// folded into final normalization; head-concat folded into store address.
// ---------------------------------------------------------------------------
#define ATQ 128
#define ATK 64
#define SQP 68   // sQ/sK/sP row stride: frag banks (4g+tg)%32 conflict-free
#define SVP 72   // sV row stride: frag banks (8tg+g)%32 conflict-free

__global__ __launch_bounds__(128) void attn_kernel() {
    extern __shared__ float sm[];
    float* sQ = sm;                       // ATQ x SQP
    float* sK = sQ + ATQ * SQP;           // ATK x SQP
    float* sV = sK + ATK * SQP;           // ATK x SVP
    float* sP = sV + ATK * SVP;           // ATQ x SQP

    const int b = blockIdx.z;
    const int h = blockIdx.y;
    const int q0 = blockIdx.x * ATQ;

    const float* Qh = g_qp + ((size_t)b * HH + h) * SS * DHV;
    const float* Kh = g_kp + ((size_t)b * HH + h) * SS * DHV;
    const float* Vh = g_vp + ((size_t)b * HH + h) * SS * DHV;

    const int tid = threadIdx.x;
    const int lane = tid & 31;
    const int warp = tid >> 5;
    const int g = lane >> 2;
    const int tg = lane & 3;

    // Load + convert Q tile: 128 x 64
#pragma unroll
    for (int i = 0; i < 16; i++) {
        int linear = tid + i * 128;
        int row = linear >> 4;
        int c4 = (linear & 15) * 4;
        float4 a4 = *(const float4*)&Qh[(size_t)(q0 + row) * DHV + c4];
        sQ[row * SQP + c4 + 0] = __uint_as_float(f2tf32(a4.x));
        sQ[row * SQP + c4 + 1] = __uint_as_float(f2tf32(a4.y));
        sQ[row * SQP + c4 + 2] = __uint_as_float(f2tf32(a4.z));
        sQ[row * SQP + c4 + 3] = __uint_as_float(f2tf32(a4.w));
    }

    float m[2][2], l[2][2], o[2][8][4];
#pragma unroll
    for (int mt = 0; mt < 2; mt++) {
        m[mt][0] = -1e30f; m[mt][1] = -1e30f;
        l[mt][0] = 0.f;    l[mt][1] = 0.f;
#pragma unroll
        for (int nt = 0; nt < 8; nt++)
#pragma unroll
            for (int e = 0; e < 4; e++) o[mt][nt][e] = 0.f;
    }

    for (int t = 0; t < SS; t += ATK) {
        __syncthreads();
        // Load K, V tiles (64 x 64 each)
#pragma unroll
        for (int i = 0; i < 8; i++) {
            int linear = tid + i * 128;
            int row = linear >> 4;
            int c4 = (linear & 15) * 4;
            float4 k4 = *(const float4*)&Kh[(size_t)(t + row) * DHV + c4];
            sK[row * SQP + c4 + 0] = __uint_as_float(f2tf32(k4.x));
            sK[row * SQP + c4 + 1] = __uint_as_float(f2tf32(k4.y));
            sK[row * SQP + c4 + 2] = __uint_as_float(f2tf32(k4.z));
            sK[row * SQP + c4 + 3] = __uint_as_float(f2tf32(k4.w));
            float4 v4 = *(const float4*)&Vh[(size_t)(t + row) * DHV + c4];
            sV[row * SVP + c4 + 0] = __uint_as_float(f2tf32(v4.x));
            sV[row * SVP + c4 + 1] = __uint_as_float(f2tf32(v4.y));
            sV[row * SVP + c4 + 2] = __uint_as_float(f2tf32(v4.z));
            sV[row * SVP + c4 + 3] = __uint_as_float(f2tf32(v4.w));
        }
        __syncthreads();

        // --- scores: S = Q @ K^T ---
        float s[2][8][4];
#pragma unroll
        for (int mt = 0; mt < 2; mt++)
#pragma unroll
            for (int nt = 0; nt < 8; nt++)
#pragma unroll
                for (int e = 0; e < 4; e++) s[mt][nt][e] = 0.f;

#pragma unroll
        for (int ks = 0; ks < 8; ks++) {
            const int kk = ks * 8;
            uint32_t qa[2][4];
#pragma unroll
            for (int mt = 0; mt < 2; mt++) {
                const int r = warp * 32 + mt * 16;
                qa[mt][0] = __float_as_uint(sQ[(r + g) * SQP + kk + tg]);
                qa[mt][1] = __float_as_uint(sQ[(r + g + 8) * SQP + kk + tg]);
                qa[mt][2] = __float_as_uint(sQ[(r + g) * SQP + kk + tg + 4]);
                qa[mt][3] = __float_as_uint(sQ[(r + g + 8) * SQP + kk + tg + 4]);
            }
#pragma unroll
            for (int nt = 0; nt < 8; nt++) {
                uint32_t kb[2];
                kb[0] = __float_as_uint(sK[(nt * 8 + g) * SQP + kk + tg]);
                kb[1] = __float_as_uint(sK[(nt * 8 + g) * SQP + kk + tg + 4]);
                mma_tf32(s[0][nt], qa[0], kb);
                mma_tf32(s[1][nt], qa[1], kb);
            }
        }

        // --- online softmax (rows g and g+8 of each m-tile; row split over quad) ---
#pragma unroll
        for (int mt = 0; mt < 2; mt++) {
            const int r = warp * 32 + mt * 16;
            float mx0 = -1e30f, mx1 = -1e30f;
#pragma unroll
            for (int nt = 0; nt < 8; nt++) {
                mx0 = fmaxf(mx0, fmaxf(s[mt][nt][0], s[mt][nt][1]));
                mx1 = fmaxf(mx1, fmaxf(s[mt][nt][2], s[mt][nt][3]));
            }
            mx0 = fmaxf(mx0, __shfl_xor_sync(0xffffffffu, mx0, 1));
            mx0 = fmaxf(mx0, __shfl_xor_sync(0xffffffffu, mx0, 2));
            mx1 = fmaxf(mx1, __shfl_xor_sync(0xffffffffu, mx1, 1));
            mx1 = fmaxf(mx1, __shfl_xor_sync(0xffffffffu, mx1, 2));

            const float mn0 = fmaxf(m[mt][0], mx0);
            const float mn1 = fmaxf(m[mt][1], mx1);
            const float al0 = __expf(m[mt][0] - mn0);
            const float al1 = __expf(m[mt][1] - mn1);
            m[mt][0] = mn0; m[mt][1] = mn1;

            float sum0 = 0.f, sum1 = 0.f;
#pragma unroll
            for (int nt = 0; nt < 8; nt++) {
                float e0 = __expf(s[mt][nt][0] - mn0);
                float e1 = __expf(s[mt][nt][1] - mn0);
                float e2 = __expf(s[mt][nt][2] - mn1);
                float e3 = __expf(s[mt][nt][3] - mn1);
                sum0 += e0 + e1;
                sum1 += e2 + e3;
                const int c = nt * 8 + 2 * tg;
                sP[(r + g) * SQP + c]     = __uint_as_float(f2tf32(e0));
                sP[(r + g) * SQP + c + 1] = __uint_as_float(f2tf32(e1));
                sP[(r + g + 8) * SQP + c]     = __uint_as_float(f2tf32(e2));
                sP[(r + g + 8) * SQP + c + 1] = __uint_as_float(f2tf32(e3));
            }
            sum0 += __shfl_xor_sync(0xffffffffu, sum0, 1);
            sum0 += __shfl_xor_sync(0xffffffffu, sum0, 2);
            sum1 += __shfl_xor_sync(0xffffffffu, sum1, 1);
            sum1 += __shfl_xor_sync(0xffffffffu, sum1, 2);
            l[mt][0] = l[mt][0] * al0 + sum0;
            l[mt][1] = l[mt][1] * al1 + sum1;

#pragma unroll
            for (int nt = 0; nt < 8; nt++) {
                o[mt][nt][0] *= al0; o[mt][nt][1] *= al0;
                o[mt][nt][2] *= al1; o[mt][nt][3] *= al1;
            }
        }
        __syncwarp();  // P rows are warp-private; order smem writes vs reads

        // --- O += P @ V ---
#pragma unroll
        for (int ks = 0; ks < 8; ks++) {
            const int kk = ks * 8;
            uint32_t pa[2][4];
#pragma unroll
            for (int mt = 0; mt < 2; mt++) {
                const int r = warp * 32 + mt * 16;
                pa[mt][0] = __float_as_uint(sP[(r + g) * SQP + kk + tg]);
                pa[mt][1] = __float_as_uint(sP[(r + g + 8) * SQP + kk + tg]);
                pa[mt][2] = __float_as_uint(sP[(r + g) * SQP + kk + tg + 4]);
                pa[mt][3] = __float_as_uint(sP[(r + g + 8) * SQP + kk + tg + 4]);
            }
#pragma unroll
            for (int nt = 0; nt < 8; nt++) {
                uint32_t vb[2];
                vb[0] = __float_as_uint(sV[(kk + tg) * SVP + nt * 8 + g]);
                vb[1] = __float_as_uint(sV[(kk + tg + 4) * SVP + nt * 8 + g]);
                mma_tf32(o[0][nt], pa[0], vb);
                mma_tf32(o[1][nt], pa[1], vb);
            }
        }
    }

    // epilogue: ctx[b][s][h*64+d] = O / (l * 8)
#pragma unroll
    for (int mt = 0; mt < 2; mt++) {
        const float inv0 = 1.0f / (l[mt][0] * 8.0f);
        const float inv1 = 1.0f / (l[mt][1] * 8.0f);
        const int row0 = q0 + warp * 32 + mt * 16 + g;
#pragma unroll
        for (int nt = 0; nt < 8; nt++) {
            const int col = h * DHV + nt * 8 + 2 * tg;
            float2 a, c;
            a.x = o[mt][nt][0] * inv0; a.y = o[mt][nt][1] * inv0;
            c.x = o[mt][nt][2] * inv1; c.y = o[mt][nt][3] * inv1;
            *(float2*)&g_ctx[((size_t)b * SS + row0) * HIDV + col] = a;
            *(float2*)&g_ctx[((size_t)b * SS + row0 + 8) * HIDV + col] = c;
        }
    }
}

// ---------------------------------------------------------------------------
extern "C" void kernel_launch(void* const* d_in, const int* in_sizes, int n_in,
                              void* d_out, int out_size) {
    (void)in_sizes; (void)n_in; (void)out_size;
    const float* q  = (const float*)d_in[0];
    const float* k  = (const float*)d_in[1];
    const float* v  = (const float*)d_in[2];
    const float* Wq = (const float*)d_in[3];
    const float* bq = (const float*)d_in[4];
    const float* Wk = (const float*)d_in[5];
    const float* bk = (const float*)d_in[6];
    const float* Wv = (const float*)d_in[7];
    const float* bv = (const float*)d_in[8];
    const float* Wo = (const float*)d_in[9];
    const float* bo = (const float*)d_in[10];
    float* out = (float*)d_out;

    dim3 pg(BB * SS / 128, HIDV / 128, 3);
    proj_kernel<<<pg, 256>>>(q, k, v, Wq, bq, Wk, bk, Wv, bv);

    const size_t smem =
        (size_t)(ATQ * SQP + ATK * SQP + ATK * SVP + ATQ * SQP) * sizeof(float);
    cudaFuncSetAttribute(attn_kernel, cudaFuncAttributeMaxDynamicSharedMemorySize,
                         (int)smem);
    attn_kernel<<<dim3(SS / ATQ, HH, BB), 128, smem>>>();

    dim3 og(BB * SS / 128, DD / 128, 1);
    out_gemm_kernel<<<og, 256>>>(Wo, bo, out);
}

// round 3
// speedup vs baseline: 4.8867x; 1.0001x over previous
#include <cuda_runtime.h>
#include <math.h>
#include <stdint.h>

// Problem constants
#define BB  2
#define SS  2048
#define DD  512
#define HH  8
#define HIDV 512
#define DHV 64

// Scratch
__device__ float g_qp[BB * SS * HIDV];
__device__ float g_kp[BB * SS * HIDV];
__device__ float g_vp[BB * SS * HIDV];
__device__ float g_ctx[BB * SS * HIDV];

// ---------------------------------------------------------------------------
// tf32 helpers
// ---------------------------------------------------------------------------
__device__ __forceinline__ uint32_t f2tf32(float x) {
    uint32_t u;
    asm("cvt.rna.tf32.f32 %0, %1;" : "=r"(u) : "f"(x));
    return u;
}

__device__ __forceinline__ void mma_tf32(float c[4], const uint32_t a[4],
                                         const uint32_t b[2]) {
    asm volatile(
        "mma.sync.aligned.m16n8k8.row.col.f32.tf32.tf32.f32 "
        "{%0,%1,%2,%3}, {%4,%5,%6,%7}, {%8,%9}, {%0,%1,%2,%3};"
        : "+f"(c[0]), "+f"(c[1]), "+f"(c[2]), "+f"(c[3])
        : "r"(a[0]), "r"(a[1]), "r"(a[2]), "r"(a[3]), "r"(b[0]), "r"(b[1]));
}

// ---------------------------------------------------------------------------
// tf32 GEMM: C[M,N] = A[M,K] @ W[K,N] + bias
// 128x128x32 block tile, 8 warps (2x4), warp tile 64x32 (4 m-tiles x 4 n-tiles)
// ---------------------------------------------------------------------------
#define GSA 36    // sA row stride (bank-conflict-free frag loads: (4g+tig)%32)
#define GSB 136   // sB row stride (bank-conflict-free: (8*tig+g)%32)

__device__ __forceinline__ void gemm_tf32_body(const float* __restrict__ A,
                                               const float* __restrict__ W,
                                               const float* __restrict__ bias,
                                               float* __restrict__ C,
                                               int M, int N, int K) {
    __shared__ float sA[128][GSA];
    __shared__ float sB[32][GSB];

    const int tid = threadIdx.x;
    const int lane = tid & 31;
    const int warp = tid >> 5;
    const int g = lane >> 2;       // groupID 0..7
    const int tg = lane & 3;       // threadID_in_group 0..3
    const int wr = warp >> 2;      // 0..1
    const int wc = warp & 3;       // 0..3

    const int brow = blockIdx.x * 128;
    const int bcol = blockIdx.y * 128;

    float acc[4][4][4];
#pragma unroll
    for (int mt = 0; mt < 4; mt++)
#pragma unroll
        for (int nt = 0; nt < 4; nt++)
#pragma unroll
            for (int e = 0; e < 4; e++) acc[mt][nt][e] = 0.f;

    for (int k0 = 0; k0 < K; k0 += 32) {
        // A tile: 128 rows x 32 cols
#pragma unroll
        for (int i = 0; i < 4; i++) {
            int linear = tid + i * 256;
            int row = linear >> 3;
            int c4 = (linear & 7) * 4;
            float4 a4 = *(const float4*)&A[(size_t)(brow + row) * K + k0 + c4];
            sA[row][c4 + 0] = __uint_as_float(f2tf32(a4.x));
            sA[row][c4 + 1] = __uint_as_float(f2tf32(a4.y));
            sA[row][c4 + 2] = __uint_as_float(f2tf32(a4.z));
            sA[row][c4 + 3] = __uint_as_float(f2tf32(a4.w));
        }
        // B tile: 32 rows x 128 cols
#pragma unroll
        for (int i = 0; i < 4; i++) {
            int linear = tid + i * 256;
            int row = linear >> 5;
            int c4 = (linear & 31) * 4;
            float4 b4 = *(const float4*)&W[(size_t)(k0 + row) * N + bcol + c4];
            sB[row][c4 + 0] = __uint_as_float(f2tf32(b4.x));
            sB[row][c4 + 1] = __uint_as_float(f2tf32(b4.y));
            sB[row][c4 + 2] = __uint_as_float(f2tf32(b4.z));
            sB[row][c4 + 3] = __uint_as_float(f2tf32(b4.w));
        }
        __syncthreads();

#pragma unroll
        for (int ks = 0; ks < 4; ks++) {
            const int kk = ks * 8;
            uint32_t af[4][4];
#pragma unroll
            for (int mt = 0; mt < 4; mt++) {
                const int r = wr * 64 + mt * 16;
                af[mt][0] = __float_as_uint(sA[r + g][kk + tg]);
                af[mt][1] = __float_as_uint(sA[r + g + 8][kk + tg]);
                af[mt][2] = __float_as_uint(sA[r + g][kk + tg + 4]);
                af[mt][3] = __float_as_uint(sA[r + g + 8][kk + tg + 4]);
            }
#pragma unroll
            for (int nt = 0; nt < 4; nt++) {
                const int c = wc * 32 + nt * 8;
                uint32_t bf[2];
                bf[0] = __float_as_uint(sB[kk + tg][c + g]);
                bf[1] = __float_as_uint(sB[kk + tg + 4][c + g]);
#pragma unroll
                for (int mt = 0; mt < 4; mt++) mma_tf32(acc[mt][nt], af[mt], bf);
            }
        }
        __syncthreads();
    }

    // epilogue + bias
#pragma unroll
    for (int mt = 0; mt < 4; mt++) {
        const int r0 = brow + wr * 64 + mt * 16 + g;
#pragma unroll
        for (int nt = 0; nt < 4; nt++) {
            const int c = bcol + wc * 32 + nt * 8 + 2 * tg;
            float2 b2 = *(const float2*)&bias[c];
            float2 o0, o1;
            o0.x = acc[mt][nt][0] + b2.x;
            o0.y = acc[mt][nt][1] + b2.y;
            o1.x = acc[mt][nt][2] + b2.x;
            o1.y = acc[mt][nt][3] + b2.y;
            *(float2*)&C[(size_t)r0 * N + c] = o0;
            *(float2*)&C[(size_t)(r0 + 8) * N + c] = o1;
        }
    }
}

__global__ __launch_bounds__(256) void proj_kernel(
    const float* __restrict__ q, const float* __restrict__ k, const float* __restrict__ v,
    const float* __restrict__ Wq, const float* __restrict__ bq,
    const float* __restrict__ Wk, const float* __restrict__ bk,
    const float* __restrict__ Wv, const float* __restrict__ bv) {
    const float* A; const float* W; const float* bias; float* C;
    if (blockIdx.z == 0)      { A = q; W = Wq; bias = bq; C = g_qp; }
    else if (blockIdx.z == 1) { A = k; W = Wk; bias = bk; C = g_kp; }
    else                      { A = v; W = Wv; bias = bv; C = g_vp; }
    gemm_tf32_body(A, W, bias, C, BB * SS, HIDV, DD);
}

__global__ __launch_bounds__(256) void out_gemm_kernel(
    const float* __restrict__ Wo, const float* __restrict__ bo, float* __restrict__ out) {
    gemm_tf32_body(g_ctx, Wo, bo, out, BB * SS, DD, HIDV);
}

// ---------------------------------------------------------------------------
// Flash attention with tf32 mma.
// Block: 128 q-rows, 4 warps (each 32 rows = 2 m-tiles), KV tiles of 64.
// Head h of batch b = contiguous slab (raw reshape). /sqrt(64) after softmax
// folded into final normalization; head-concat folded into store address.
// ---------------------------------------------------------------------------
#define ATQ 128
#define ATK 64
#define SQP 68   // sQ/sK/sP row stride: frag banks (4g+tg)%32 conflict-free
#define SVP 72   // sV row stride: frag banks (8tg+g)%32 conflict-free

__global__ __launch_bounds__(128) void attn_kernel() {
    extern __shared__ float sm[];
    float* sQ = sm;                       // ATQ x SQP
    float* sK = sQ + ATQ * SQP;           // ATK x SQP
    float* sV = sK + ATK * SQP;           // ATK x SVP
    float* sP = sV + ATK * SVP;           // ATQ x SQP

    const int b = blockIdx.z;
    const int h = blockIdx.y;
    const int q0 = blockIdx.x * ATQ;

    const float* Qh = g_qp + ((size_t)b * HH + h) * SS * DHV;
    const float* Kh = g_kp + ((size_t)b * HH + h) * SS * DHV;
    const float* Vh = g_vp + ((size_t)b * HH + h) * SS * DHV;

    const int tid = threadIdx.x;
    const int lane = tid & 31;
    const int warp = tid >> 5;
    const int g = lane >> 2;
    const int tg = lane & 3;

    // Load + convert Q tile: 128 x 64
#pragma unroll
    for (int i = 0; i < 16; i++) {
        int linear = tid + i * 128;
        int row = linear >> 4;
        int c4 = (linear & 15) * 4;
        float4 a4 = *(const float4*)&Qh[(size_t)(q0 + row) * DHV + c4];
        sQ[row * SQP + c4 + 0] = __uint_as_float(f2tf32(a4.x));
        sQ[row * SQP + c4 + 1] = __uint_as_float(f2tf32(a4.y));
        sQ[row * SQP + c4 + 2] = __uint_as_float(f2tf32(a4.z));
        sQ[row * SQP + c4 + 3] = __uint_as_float(f2tf32(a4.w));
    }

    float m[2][2], l[2][2], o[2][8][4];
#pragma unroll
    for (int mt = 0; mt < 2; mt++) {
        m[mt][0] = -1e30f; m[mt][1] = -1e30f;
        l[mt][0] = 0.f;    l[mt][1] = 0.f;
#pragma unroll
        for (int nt = 0; nt < 8; nt++)
#pragma unroll
            for (int e = 0; e < 4; e++) o[mt][nt][e] = 0.f;
    }

    for (int t = 0; t < SS; t += ATK) {
        __syncthreads();
        // Load K, V tiles (64 x 64 each)
#pragma unroll
        for (int i = 0; i < 8; i++) {
            int linear = tid + i * 128;
            int row = linear >> 4;
            int c4 = (linear & 15) * 4;
            float4 k4 = *(const float4*)&Kh[(size_t)(t + row) * DHV + c4];
            sK[row * SQP + c4 + 0] = __uint_as_float(f2tf32(k4.x));
            sK[row * SQP + c4 + 1] = __uint_as_float(f2tf32(k4.y));
            sK[row * SQP + c4 + 2] = __uint_as_float(f2tf32(k4.z));
            sK[row * SQP + c4 + 3] = __uint_as_float(f2tf32(k4.w));
            float4 v4 = *(const float4*)&Vh[(size_t)(t + row) * DHV + c4];
            sV[row * SVP + c4 + 0] = __uint_as_float(f2tf32(v4.x));
            sV[row * SVP + c4 + 1] = __uint_as_float(f2tf32(v4.y));
            sV[row * SVP + c4 + 2] = __uint_as_float(f2tf32(v4.z));
            sV[row * SVP + c4 + 3] = __uint_as_float(f2tf32(v4.w));
        }
        __syncthreads();

        // --- scores: S = Q @ K^T ---
        float s[2][8][4];
#pragma unroll
        for (int mt = 0; mt < 2; mt++)
#pragma unroll
            for (int nt = 0; nt < 8; nt++)
#pragma unroll
                for (int e = 0; e < 4; e++) s[mt][nt][e] = 0.f;

#pragma unroll
        for (int ks = 0; ks < 8; ks++) {
            const int kk = ks * 8;
            uint32_t qa[2][4];
#pragma unroll
            for (int mt = 0; mt < 2; mt++) {
                const int r = warp * 32 + mt * 16;
                qa[mt][0] = __float_as_uint(sQ[(r + g) * SQP + kk + tg]);
                qa[mt][1] = __float_as_uint(sQ[(r + g + 8) * SQP + kk + tg]);
                qa[mt][2] = __float_as_uint(sQ[(r + g) * SQP + kk + tg + 4]);
                qa[mt][3] = __float_as_uint(sQ[(r + g + 8) * SQP + kk + tg + 4]);
            }
#pragma unroll
            for (int nt = 0; nt < 8; nt++) {
                uint32_t kb[2];
                kb[0] = __float_as_uint(sK[(nt * 8 + g) * SQP + kk + tg]);
                kb[1] = __float_as_uint(sK[(nt * 8 + g) * SQP + kk + tg + 4]);
                mma_tf32(s[0][nt], qa[0], kb);
                mma_tf32(s[1][nt], qa[1], kb);
            }
        }

        // --- online softmax (rows g and g+8 of each m-tile; row split over quad) ---
#pragma unroll
        for (int mt = 0; mt < 2; mt++) {
            const int r = warp * 32 + mt * 16;
            float mx0 = -1e30f, mx1 = -1e30f;
#pragma unroll
            for (int nt = 0; nt < 8; nt++) {
                mx0 = fmaxf(mx0, fmaxf(s[mt][nt][0], s[mt][nt][1]));
                mx1 = fmaxf(mx1, fmaxf(s[mt][nt][2], s[mt][nt][3]));
            }
            mx0 = fmaxf(mx0, __shfl_xor_sync(0xffffffffu, mx0, 1));
            mx0 = fmaxf(mx0, __shfl_xor_sync(0xffffffffu, mx0, 2));
            mx1 = fmaxf(mx1, __shfl_xor_sync(0xffffffffu, mx1, 1));
            mx1 = fmaxf(mx1, __shfl_xor_sync(0xffffffffu, mx1, 2));

            const float mn0 = fmaxf(m[mt][0], mx0);
            const float mn1 = fmaxf(m[mt][1], mx1);
            const float al0 = __expf(m[mt][0] - mn0);
            const float al1 = __expf(m[mt][1] - mn1);
            m[mt][0] = mn0; m[mt][1] = mn1;

            float sum0 = 0.f, sum1 = 0.f;
#pragma unroll
            for (int nt = 0; nt < 8; nt++) {
                float e0 = __expf(s[mt][nt][0] - mn0);
                float e1 = __expf(s[mt][nt][1] - mn0);
                float e2 = __expf(s[mt][nt][2] - mn1);
                float e3 = __expf(s[mt][nt][3] - mn1);
                sum0 += e0 + e1;
                sum1 += e2 + e3;
                const int c = nt * 8 + 2 * tg;
                sP[(r + g) * SQP + c]     = __uint_as_float(f2tf32(e0));
                sP[(r + g) * SQP + c + 1] = __uint_as_float(f2tf32(e1));
                sP[(r + g + 8) * SQP + c]     = __uint_as_float(f2tf32(e2));
                sP[(r + g + 8) * SQP + c + 1] = __uint_as_float(f2tf32(e3));
            }
            sum0 += __shfl_xor_sync(0xffffffffu, sum0, 1);
            sum0 += __shfl_xor_sync(0xffffffffu, sum0, 2);
            sum1 += __shfl_xor_sync(0xffffffffu, sum1, 1);
            sum1 += __shfl_xor_sync(0xffffffffu, sum1, 2);
            l[mt][0] = l[mt][0] * al0 + sum0;
            l[mt][1] = l[mt][1] * al1 + sum1;

#pragma unroll
            for (int nt = 0; nt < 8; nt++) {
                o[mt][nt][0] *= al0; o[mt][nt][1] *= al0;
                o[mt][nt][2] *= al1; o[mt][nt][3] *= al1;
            }
        }
        __syncwarp();  // P rows are warp-private; order smem writes vs reads

        // --- O += P @ V ---
#pragma unroll
        for (int ks = 0; ks < 8; ks++) {
            const int kk = ks * 8;
            uint32_t pa[2][4];
#pragma unroll
            for (int mt = 0; mt < 2; mt++) {
                const int r = warp * 32 + mt * 16;
                pa[mt][0] = __float_as_uint(sP[(r + g) * SQP + kk + tg]);
                pa[mt][1] = __float_as_uint(sP[(r + g + 8) * SQP + kk + tg]);
                pa[mt][2] = __float_as_uint(sP[(r + g) * SQP + kk + tg + 4]);
                pa[mt][3] = __float_as_uint(sP[(r + g + 8) * SQP + kk + tg + 4]);
            }
#pragma unroll
            for (int nt = 0; nt < 8; nt++) {
                uint32_t vb[2];
                vb[0] = __float_as_uint(sV[(kk + tg) * SVP + nt * 8 + g]);
                vb[1] = __float_as_uint(sV[(kk + tg + 4) * SVP + nt * 8 + g]);
                mma_tf32(o[0][nt], pa[0], vb);
                mma_tf32(o[1][nt], pa[1], vb);
            }
        }
    }

    // epilogue: ctx[b][s][h*64+d] = O / (l * 8)
#pragma unroll
    for (int mt = 0; mt < 2; mt++) {
        const float inv0 = 1.0f / (l[mt][0] * 8.0f);
        const float inv1 = 1.0f / (l[mt][1] * 8.0f);
        const int row0 = q0 + warp * 32 + mt * 16 + g;
#pragma unroll
        for (int nt = 0; nt < 8; nt++) {
            const int col = h * DHV + nt * 8 + 2 * tg;
            float2 a, c;
            a.x = o[mt][nt][0] * inv0; a.y = o[mt][nt][1] * inv0;
            c.x = o[mt][nt][2] * inv1; c.y = o[mt][nt][3] * inv1;
            *(float2*)&g_ctx[((size_t)b * SS + row0) * HIDV + col] = a;
            *(float2*)&g_ctx[((size_t)b * SS + row0 + 8) * HIDV + col] = c;
        }
    }
}

// ---------------------------------------------------------------------------
extern "C" void kernel_launch(void* const* d_in, const int* in_sizes, int n_in,
                              void* d_out, int out_size) {
    (void)in_sizes; (void)n_in; (void)out_size;
    const float* q  = (const float*)d_in[0];
    const float* k  = (const float*)d_in[1];
    const float* v  = (const float*)d_in[2];
    const float* Wq = (const float*)d_in[3];
    const float* bq = (const float*)d_in[4];
    const float* Wk = (const float*)d_in[5];
    const float* bk = (const float*)d_in[6];
    const float* Wv = (const float*)d_in[7];
    const float* bv = (const float*)d_in[8];
    const float* Wo = (const float*)d_in[9];
    const float* bo = (const float*)d_in[10];
    float* out = (float*)d_out;

    dim3 pg(BB * SS / 128, HIDV / 128, 3);
    proj_kernel<<<pg, 256>>>(q, k, v, Wq, bq, Wk, bk, Wv, bv);

    const size_t smem =
        (size_t)(ATQ * SQP + ATK * SQP + ATK * SVP + ATQ * SQP) * sizeof(float);
    cudaFuncSetAttribute(attn_kernel, cudaFuncAttributeMaxDynamicSharedMemorySize,
                         (int)smem);
    attn_kernel<<<dim3(SS / ATQ, HH, BB), 128, smem>>>();

    dim3 og(BB * SS / 128, DD / 128, 1);
    out_gemm_kernel<<<og, 256>>>(Wo, bo, out);
}